// round 7
// baseline (speedup 1.0000x reference)
#include <cuda_runtime.h>
#include <cuda_bf16.h>

// FQCNN_layer: closed-form evaluation.
//
// Math: expval(Z on wire 4) is invariant under the post-encoding circuit
// (H on wire 5, controlled-U3s on wire 6) since those are unitaries acting on
// wires != 4 (controls never mix control-wire amplitudes, so the wire-4
// marginal is preserved). After H^{x4} on wires 0-3 and the commuting
// (controlled-)RYs on wire 4, summing the 16 equal-weight control branches:
//   <Z> = (1/16) * [ 8 cos(p0) + 2 cos(p0+p1) + 2 cos(p0+p2) + cos(p0+p3)
//                   + cos(p0+p1+p3) + cos(p0+p2+p3) + cos(p0+p1+p2+p3) ]
// with (p0,p1,p2,p3) = (im[j,k], im[j,k+1], im[j+1,k], im[j+1,k+1]).
// U3_w is provably unused.
//
// R4: one output per thread (196608 threads, 768 blocks) to double resident
// warps/SM vs R3 — this kernel is DRAM-latency-bound, not BW-bound.

#define N_OUT 196608   // 16*3*64*64

__global__ __launch_bounds__(256) void fqcnn_kernel(const float2* __restrict__ in2,
                                                    float* __restrict__ out) {
    int i = blockIdx.x * blockDim.x + threadIdx.x;
    if (i >= N_OUT) return;

    int ow = i & 63;           // output column
    int oh = (i >> 6) & 63;    // output row
    int bc = i >> 12;          // batch*channel plane

    // input viewed as [bc][128 rows][64 float2 per row]
    int base = (bc * 128 + 2 * oh) * 64 + ow;
    const float2 r0 = in2[base];        // row 2*oh   : p0 p1
    const float2 r1 = in2[base + 64];   // row 2*oh+1 : p2 p3

    float p0 = r0.x, p1 = r0.y, p2 = r1.x, p3 = r1.y;

    float s = 8.0f * __cosf(p0)
            + 2.0f * __cosf(p0 + p1)
            + 2.0f * __cosf(p0 + p2)
            +        __cosf(p0 + p3)
            +        __cosf(p0 + p1 + p3)
            +        __cosf(p0 + p2 + p3)
            +        __cosf(p0 + p1 + p2 + p3);

    out[i] = s * 0.0625f;
}

extern "C" void kernel_launch(void* const* d_in, const int* in_sizes, int n_in,
                              void* d_out, int out_size) {
    const float2* x  = (const float2*)d_in[0];   // [16,3,128,128] fp32
    // d_in[1] = U3_w — unused (see math above)
    float* out = (float*)d_out;                  // [16,3,64,64] fp32

    const int threads = 256;
    const int blocks  = (N_OUT + threads - 1) / threads;  // 768
    fqcnn_kernel<<<blocks, threads>>>(x, out);
}

// round 8
// speedup vs baseline: 1.0240x; 1.0240x over previous
#include <cuda_runtime.h>
#include <cuda_bf16.h>

// FQCNN_layer: closed-form evaluation.
//
// Math: expval(Z on wire 4) is invariant under the post-encoding circuit
// (H on wire 5, controlled-U3s on wire 6: unitaries on wires != 4 preserve
// the wire-4 marginal). Summing the 16 equal-weight H^{x4} branches of the
// commuting (controlled-)RYs on wire 4:
//   <Z> = (1/16)[ 8cos(A) + 2cos(A+u) + 2cos(A+v) + cos(A+w)
//                + cos(A+u+w) + cos(A+v+w) + cos(A+u+v+w) ]
// with (A,u,v,w) = (im[j,k], im[j,k+1], im[j+1,k], im[j+1,k+1]).
// Sum-to-product (exact):
//   2c(A+u)+2c(A+v)               = 4 c((u-v)/2) c(A+m),  m=(u+v)/2
//   c(A+w)+c(A+u+w)+c(A+v+w)+c(A+u+v+w) = 4 c(u/2) c(v/2) c(A+m+w)
// => out = 0.5 c(A) + 0.25 [ c((u-v)/2) c(A+m) + c(u/2) c(v/2) c(A+m+w) ]
// (6 MUFU.COS instead of 7). U3_w is provably unused.
//
// R7: 128-thread blocks (1536 CTAs) to shrink the last-wave tail; kernel is
// ramp/latency-floor bound (DRAM 8%, fma 2.5%), not BW or occupancy bound.

#define N_OUT 196608   // 16*3*64*64

__global__ __launch_bounds__(128) void fqcnn_kernel(const float2* __restrict__ in2,
                                                    float* __restrict__ out) {
    int i = blockIdx.x * blockDim.x + threadIdx.x;
    if (i >= N_OUT) return;

    int ow = i & 63;           // output column
    int oh = (i >> 6) & 63;    // output row
    int bc = i >> 12;          // batch*channel plane

    // input viewed as [bc][128 rows][64 float2 per row]
    int base = (bc * 128 + 2 * oh) * 64 + ow;
    const float2 r0 = in2[base];        // row 2*oh   : A u
    const float2 r1 = in2[base + 64];   // row 2*oh+1 : v w

    float A = r0.x, u = r0.y, v = r1.x, w = r1.y;

    float hu = 0.5f * u;
    float hv = 0.5f * v;
    float m  = hu + hv;
    float d  = hu - hv;

    float cA  = __cosf(A);
    float cd  = __cosf(d);
    float cm  = __cosf(A + m);
    float chu = __cosf(hu);
    float chv = __cosf(hv);
    float cw  = __cosf(A + m + w);

    out[i] = 0.5f * cA + 0.25f * (cd * cm + chu * chv * cw);
}

extern "C" void kernel_launch(void* const* d_in, const int* in_sizes, int n_in,
                              void* d_out, int out_size) {
    const float2* x  = (const float2*)d_in[0];   // [16,3,128,128] fp32
    // d_in[1] = U3_w — unused (see math above)
    float* out = (float*)d_out;                  // [16,3,64,64] fp32

    const int threads = 128;
    const int blocks  = (N_OUT + threads - 1) / threads;  // 1536
    fqcnn_kernel<<<blocks, threads>>>(x, out);
}

// round 10
// speedup vs baseline: 1.2102x; 1.1818x over previous
#include <cuda_runtime.h>
#include <cuda_bf16.h>

// FQCNN_layer: closed-form evaluation.
//
// Math: expval(Z on wire 4) is invariant under the post-encoding circuit
// (H on wire 5, controlled-U3s on wire 6: unitaries on wires != 4 preserve
// the wire-4 marginal). Summing the 16 equal-weight H^{x4} branches of the
// commuting (controlled-)RYs on wire 4:
//   <Z> = (1/16)[ 8cos(A) + 2cos(A+u) + 2cos(A+v) + cos(A+w)
//                + cos(A+u+w) + cos(A+v+w) + cos(A+u+v+w) ]
// with (A,u,v,w) = (im[j,k], im[j,k+1], im[j+1,k], im[j+1,k+1]).
// Sum-to-product (exact):
//   2c(A+u)+2c(A+v)                      = 4 c((u-v)/2) c(A+m),  m=(u+v)/2
//   c(A+w)+c(A+u+w)+c(A+v+w)+c(A+u+v+w) = 4 c(u/2) c(v/2) c(A+m+w)
// => out = 0.5 c(A) + 0.25 [ c((u-v)/2) c(A+m) + c(u/2) c(v/2) c(A+m+w) ]
// (6 MUFU.COS instead of 7). U3_w is provably unused.
//
// R8: launch shape reverted to the best-measured R4 config (256 thr x 768
// blocks, one output/thread — ncu 4.83us) + the 6-cos reduction. R7 showed
// 128-thread CTAs regress (more ramp events, lower occ) on this
// launch-overhead-floor-bound kernel.

#define N_OUT 196608   // 16*3*64*64

__global__ __launch_bounds__(256) void fqcnn_kernel(const float2* __restrict__ in2,
                                                    float* __restrict__ out) {
    int i = blockIdx.x * blockDim.x + threadIdx.x;
    if (i >= N_OUT) return;

    int ow = i & 63;           // output column
    int oh = (i >> 6) & 63;    // output row
    int bc = i >> 12;          // batch*channel plane

    // input viewed as [bc][128 rows][64 float2 per row]
    int base = (bc * 128 + 2 * oh) * 64 + ow;
    const float2 r0 = in2[base];        // row 2*oh   : A u
    const float2 r1 = in2[base + 64];   // row 2*oh+1 : v w

    float A = r0.x, u = r0.y, v = r1.x, w = r1.y;

    float hu = 0.5f * u;
    float hv = 0.5f * v;
    float m  = hu + hv;
    float d  = hu - hv;

    float cA  = __cosf(A);
    float cd  = __cosf(d);
    float cm  = __cosf(A + m);
    float chu = __cosf(hu);
    float chv = __cosf(hv);
    float cw  = __cosf(A + m + w);

    out[i] = 0.5f * cA + 0.25f * (cd * cm + chu * chv * cw);
}

extern "C" void kernel_launch(void* const* d_in, const int* in_sizes, int n_in,
                              void* d_out, int out_size) {
    const float2* x  = (const float2*)d_in[0];   // [16,3,128,128] fp32
    // d_in[1] = U3_w — unused (see math above)
    float* out = (float*)d_out;                  // [16,3,64,64] fp32

    const int threads = 256;
    const int blocks  = (N_OUT + threads - 1) / threads;  // 768
    fqcnn_kernel<<<blocks, threads>>>(x, out);
}